// round 14
// baseline (speedup 1.0000x reference)
#include <cuda_runtime.h>
#include <math.h>
#include <stdint.h>

#define BB    2
#define N0T   1024
#define N1T   1024
#define TNT   2048
#define HH    16
#define DDH   64
#define DI    1024
#define DIM0  1024
#define DIM1  768

// ---------------- device scratch ----------------
__device__ float g_q  [(size_t)BB * HH * TNT * DDH];   // (B,H,TN,D); flat per-b (2048,1024) == reference q-reshape
__device__ float g_k  [(size_t)BB * HH * TNT * DDH];
__device__ float g_v  [(size_t)BB * HH * TNT * DDH];
__device__ float g_wt2[(size_t)HH * DI * TNT];         // (H, k=1024, j=2048)
__device__ float g_T2 [(size_t)BB * HH * TNT * TNT];   // (B,H,TN,TN)
__device__ float g_O  [(size_t)BB * TNT * DI];         // (B,TN,H*D)

// ---------------- helpers ----------------
__device__ __forceinline__ uint32_t f2tf(float f) {
    uint32_t u;
    asm("cvt.rna.tf32.f32 %0, %1;" : "=r"(u) : "f"(f));
    return u;
}
__device__ __forceinline__ void mma_tf32(float c[4],
                                         uint32_t a0, uint32_t a1, uint32_t a2, uint32_t a3,
                                         uint32_t b0, uint32_t b1) {
    asm("mma.sync.aligned.m16n8k8.row.col.f32.tf32.tf32.f32 "
        "{%0,%1,%2,%3},{%4,%5,%6,%7},{%8,%9},{%0,%1,%2,%3};"
        : "+f"(c[0]), "+f"(c[1]), "+f"(c[2]), "+f"(c[3])
        : "r"(a0), "r"(a1), "r"(a2), "r"(a3), "r"(b0), "r"(b1));
}
__device__ __forceinline__ float exp2fast(float y) {
    y = fmaxf(y, -125.f);
    float z  = y + 12582912.f;
    int   ei = __float_as_int(z) - 0x4B400000;
    float f  = y - (z - 12582912.f);
    float p  = 1.3333558e-3f;
    p = fmaf(p, f, 9.6181291e-3f);
    p = fmaf(p, f, 5.5504109e-2f);
    p = fmaf(p, f, 2.4022651e-1f);
    p = fmaf(p, f, 6.9314718e-1f);
    p = fmaf(p, f, 1.0f);
    return __int_as_float(__float_as_int(p) + (ei << 23));
}

// ---------------- w_tau transpose: (1024, j*16+h) -> (h, 1024, j) f32 ----------------
__global__ void __launch_bounds__(256) wtau_tr(const float* __restrict__ wt)
{
    __shared__ float s[512 * 17];
    const int kk = blockIdx.y;
    const int j0 = blockIdx.x * 512;
    const float* src = wt + (size_t)kk * (TNT * HH) + (size_t)j0 * HH;
    for (int t = threadIdx.x; t < 512 * 16; t += 256)
        s[(t >> 4) * 17 + (t & 15)] = src[t];
    __syncthreads();
    for (int t = threadIdx.x; t < 512 * 16; t += 256) {
        int h = t >> 9;
        int j = t & 511;
        g_wt2[(size_t)h * (DI * TNT) + (size_t)kk * TNT + j0 + j] = s[j * 17 + h];
    }
}

// ---------------- tau GEMM: 128x128 tile, K-chunk 32, single-sync double buffer ----------------
// grid (16 j, 16 i, 32 z=b*16+h), 256 threads, warp tile 64x32, 2 CTAs/SM.
#define SAW 36                         // A smem stride (floats), conflict-free frags
#define SBW 136                        // B smem stride (floats), conflict-free frags
#define TAU_STAGE (128 * SAW + 32 * SBW)   // 8960 floats per stage
#define NIT32 32
__global__ void __launch_bounds__(256, 2) tau_k(const float* __restrict__ btau)
{
    extern __shared__ __align__(16) float smem[];
    float* sbias = smem + 2 * TAU_STAGE;   // [128]

    const int tid  = threadIdx.x;
    const int lane = tid & 31, wid = tid >> 5;
    const int wm = wid >> 2, wn = wid & 3;
    const int g  = lane >> 2, tg = lane & 3;

    const int j0 = blockIdx.x * 128;
    const int i0 = blockIdx.y * 128;
    const int z  = blockIdx.z;
    const int b  = z >> 4, h = z & 15;

    const float* Ab = g_q   + (size_t)b * (TNT * DI) + (size_t)i0 * DI;
    const float* Bb = g_wt2 + (size_t)h * (DI * TNT) + j0;

    if (tid < 128) sbias[tid] = btau[(size_t)(j0 + tid) * HH + h];

    // loader mapping (identical to the proven R2 pattern, per k16 half)
    const int ar   = tid >> 2;           // 0..63 (and +64)
    const int acol = (tid & 3) * 4;      // k within half
    const int bk   = tid >> 5;           // 0..7 (and +8)
    const int bn   = (tid & 31) * 4;
    const float* Ap  = Ab + (size_t)ar * DI + acol;
    const float* Ap2 = Ap + (size_t)64 * DI;
    const float* Bp  = Bb + (size_t)bk * TNT + bn;
    const float* Bp2 = Bp + (size_t)8 * TNT;

    float acc[4][4][4];
#pragma unroll
    for (int i = 0; i < 4; i++)
#pragma unroll
        for (int j = 0; j < 4; j++)
#pragma unroll
            for (int r = 0; r < 4; r++) acc[i][j][r] = 0.f;

    uint32_t ra[8], rb[8];

// load one k16 half starting at absolute k = K0
#define LDGH(K0)                                                                 \
    {                                                                            \
        float4 a1v = *(const float4*)(Ap  + (K0));                               \
        float4 a2v = *(const float4*)(Ap2 + (K0));                               \
        float4 b1v = *(const float4*)(Bp  + (size_t)(K0) * TNT);                 \
        float4 b2v = *(const float4*)(Bp2 + (size_t)(K0) * TNT);                 \
        ra[0]=f2tf(a1v.x); ra[1]=f2tf(a1v.y); ra[2]=f2tf(a1v.z); ra[3]=f2tf(a1v.w); \
        ra[4]=f2tf(a2v.x); ra[5]=f2tf(a2v.y); ra[6]=f2tf(a2v.z); ra[7]=f2tf(a2v.w); \
        rb[0]=f2tf(b1v.x); rb[1]=f2tf(b1v.y); rb[2]=f2tf(b1v.z); rb[3]=f2tf(b1v.w); \
        rb[4]=f2tf(b2v.x); rb[5]=f2tf(b2v.y); rb[6]=f2tf(b2v.z); rb[7]=f2tf(b2v.w); \
    }
// store held half into stage S at k-offset HOFF (0 or 16)
#define STSH(S, HOFF)                                                            \
    {                                                                            \
        uint32_t* As_ = (uint32_t*)(smem + (S) * TAU_STAGE);                     \
        uint32_t* Bs_ = (uint32_t*)(smem + (S) * TAU_STAGE + 128 * SAW);         \
        *(uint4*)&As_[ar * SAW + (HOFF) + acol]        = make_uint4(ra[0], ra[1], ra[2], ra[3]); \
        *(uint4*)&As_[(ar + 64) * SAW + (HOFF) + acol] = make_uint4(ra[4], ra[5], ra[6], ra[7]); \
        *(uint4*)&Bs_[((HOFF) + bk) * SBW + bn]        = make_uint4(rb[0], rb[1], rb[2], rb[3]); \
        *(uint4*)&Bs_[((HOFF) + bk + 8) * SBW + bn]    = make_uint4(rb[4], rb[5], rb[6], rb[7]); \
    }
// one k8 MMA phase from stage base pointers
#define MMAPH(KS)                                                                \
    {                                                                            \
        uint32_t af[4][4], bf[4][2];                                             \
        _Pragma("unroll")                                                        \
        for (int mt = 0; mt < 4; mt++) {                                         \
            const int rm = wm * 64 + mt * 16 + g;                                \
            af[mt][0] = As[rm * SAW + (KS) + tg];                                \
            af[mt][1] = As[(rm + 8) * SAW + (KS) + tg];                          \
            af[mt][2] = As[rm * SAW + (KS) + tg + 4];                            \
            af[mt][3] = As[(rm + 8) * SAW + (KS) + tg + 4];                      \
        }                                                                        \
        _Pragma("unroll")                                                        \
        for (int nt = 0; nt < 4; nt++) {                                         \
            const int cn = wn * 32 + nt * 8 + g;                                 \
            bf[nt][0] = Bs[((KS) + tg) * SBW + cn];                              \
            bf[nt][1] = Bs[((KS) + tg + 4) * SBW + cn];                          \
        }                                                                        \
        _Pragma("unroll")                                                        \
        for (int mt = 0; mt < 4; mt++)                                           \
            _Pragma("unroll")                                                    \
            for (int nt = 0; nt < 4; nt++)                                       \
                mma_tf32(acc[mt][nt], af[mt][0], af[mt][1], af[mt][2], af[mt][3],\
                         bf[nt][0], bf[nt][1]);                                  \
    }

    // prologue: fill stage 0 (both halves)
    LDGH(0);  STSH(0, 0);
    LDGH(16); STSH(0, 16);
    __syncthreads();

    int buf = 0;
    for (int it = 0; it < NIT32; it++) {
        const int k0 = it * 32;
        const bool nxt = (it + 1) < NIT32;
        const uint32_t* As = (const uint32_t*)(smem + buf * TAU_STAGE);
        const uint32_t* Bs = (const uint32_t*)(smem + buf * TAU_STAGE + 128 * SAW);

        if (nxt) LDGH(k0 + 32);
        MMAPH(0);
        MMAPH(8);
        if (nxt) { STSH(buf ^ 1, 0); LDGH(k0 + 48); }
        MMAPH(16);
        if (nxt) STSH(buf ^ 1, 16);
        MMAPH(24);
        __syncthreads();
        buf ^= 1;
    }
#undef LDGH
#undef STSH
#undef MMAPH

    // epilogue: + b_tau, write g_T2
#pragma unroll
    for (int mt = 0; mt < 4; mt++) {
        const int row0 = i0 + wm * 64 + mt * 16 + g;
#pragma unroll
        for (int nt = 0; nt < 4; nt++) {
            const int col = wn * 32 + nt * 8 + tg * 2;
            const float b0 = sbias[col], b1 = sbias[col + 1];
            float2 v0 = make_float2(acc[mt][nt][0] + b0, acc[mt][nt][1] + b1);
            float2 v1 = make_float2(acc[mt][nt][2] + b0, acc[mt][nt][3] + b1);
            float* base = g_T2 + ((size_t)z * TNT + row0) * TNT + j0 + col;
            *(float2*)base = v0;
            *(float2*)(base + (size_t)8 * TNT) = v1;
        }
    }
}

// ---------------- TF32 legacy GEMM (qkv / out), 128x128x16 ----------------
template<int MODE>
__global__ void __launch_bounds__(256, 2)
tgemm(const float* __restrict__ A, const float* __restrict__ Bm, float* __restrict__ C,
      int K, int lda, int ldb, int ldc,
      long strideA, long strideC, int aux)
{
    __shared__ uint32_t As[2][128 * 20];
    __shared__ uint32_t Bs[2][16 * 136];

    const int z = blockIdx.z;
    const float* Aeff;
    const float* Beff;
    float*       Ceff = nullptr;

    if (MODE == 2) {
        Aeff = g_O + (size_t)aux + (size_t)z * ((size_t)TNT * DI);
        Beff = Bm;
        Ceff = C + (size_t)z * strideC;
    } else {
        Aeff = A + (size_t)z * strideA;
        Beff = Bm;
    }

    const int tid  = threadIdx.x;
    const int lane = tid & 31, wid = tid >> 5;
    const int wm = wid >> 2, wn = wid & 3;
    const int g  = lane >> 2, tg = lane & 3;
    const int m0 = blockIdx.y * 128, n0 = blockIdx.x * 128;

    float acc[4][4][4];
#pragma unroll
    for (int i = 0; i < 4; i++)
#pragma unroll
        for (int j = 0; j < 4; j++)
#pragma unroll
            for (int r = 0; r < 4; r++) acc[i][j][r] = 0.f;

    const int ar   = tid >> 2;
    const int acol = (tid & 3) * 4;
    const int bk   = tid >> 5;
    const int bn   = (tid & 31) * 4;
    const float* Ap  = Aeff + (size_t)(m0 + ar) * lda + acol;
    const float* Ap2 = Ap + (size_t)64 * lda;
    const float* Bp  = Beff + (size_t)bk * ldb + n0 + bn;
    const float* Bp2 = Bp + (size_t)8 * ldb;

    uint32_t ra[8], rb[8];

#define LDGCVT(K0)                                                              \
    {                                                                           \
        float4 a1v = *(const float4*)(Ap  + (K0));                              \
        float4 a2v = *(const float4*)(Ap2 + (K0));                              \
        float4 b1v = *(const float4*)(Bp  + (size_t)(K0) * ldb);                \
        float4 b2v = *(const float4*)(Bp2 + (size_t)(K0) * ldb);                \
        ra[0]=f2tf(a1v.x); ra[1]=f2tf(a1v.y); ra[2]=f2tf(a1v.z); ra[3]=f2tf(a1v.w); \
        ra[4]=f2tf(a2v.x); ra[5]=f2tf(a2v.y); ra[6]=f2tf(a2v.z); ra[7]=f2tf(a2v.w); \
        rb[0]=f2tf(b1v.x); rb[1]=f2tf(b1v.y); rb[2]=f2tf(b1v.z); rb[3]=f2tf(b1v.w); \
        rb[4]=f2tf(b2v.x); rb[5]=f2tf(b2v.y); rb[6]=f2tf(b2v.z); rb[7]=f2tf(b2v.w); \
    }
#define STSTILE(S)                                                              \
    {                                                                           \
        *(uint4*)&As[S][ar * 20 + acol]        = make_uint4(ra[0], ra[1], ra[2], ra[3]); \
        *(uint4*)&As[S][(ar + 64) * 20 + acol] = make_uint4(ra[4], ra[5], ra[6], ra[7]); \
        *(uint4*)&Bs[S][bk * 136 + bn]         = make_uint4(rb[0], rb[1], rb[2], rb[3]); \
        *(uint4*)&Bs[S][(bk + 8) * 136 + bn]   = make_uint4(rb[4], rb[5], rb[6], rb[7]); \
    }

    LDGCVT(0);
    STSTILE(0);
    __syncthreads();

    int buf = 0;
    for (int k0 = 0; k0 < K; k0 += 16) {
        const bool nxt = (k0 + 16) < K;
        if (nxt) LDGCVT(k0 + 16);
#pragma unroll
        for (int ks = 0; ks < 16; ks += 8) {
            uint32_t af[4][4], bf[4][2];
#pragma unroll
            for (int mt = 0; mt < 4; mt++) {
                const int rm = wm * 64 + mt * 16 + g;
                af[mt][0] = As[buf][rm * 20 + ks + tg];
                af[mt][1] = As[buf][(rm + 8) * 20 + ks + tg];
                af[mt][2] = As[buf][rm * 20 + ks + tg + 4];
                af[mt][3] = As[buf][(rm + 8) * 20 + ks + tg + 4];
            }
#pragma unroll
            for (int nt = 0; nt < 4; nt++) {
                const int cn = wn * 32 + nt * 8 + g;
                bf[nt][0] = Bs[buf][(ks + tg) * 136 + cn];
                bf[nt][1] = Bs[buf][(ks + tg + 4) * 136 + cn];
            }
#pragma unroll
            for (int mt = 0; mt < 4; mt++)
#pragma unroll
                for (int nt = 0; nt < 4; nt++)
                    mma_tf32(acc[mt][nt], af[mt][0], af[mt][1], af[mt][2], af[mt][3],
                             bf[nt][0], bf[nt][1]);
        }
        if (nxt) STSTILE(buf ^ 1);
        __syncthreads();
        buf ^= 1;
    }

#pragma unroll
    for (int mt = 0; mt < 4; mt++) {
        const int row0 = m0 + wm * 64 + mt * 16 + g;
#pragma unroll
        for (int nt = 0; nt < 4; nt++) {
            const int col = n0 + wn * 32 + nt * 8 + tg * 2;
            float2 v0 = make_float2(acc[mt][nt][0], acc[mt][nt][1]);
            float2 v1 = make_float2(acc[mt][nt][2], acc[mt][nt][3]);
            if (MODE == 0) {
                const int sel = col >> 10, hh = (col >> 6) & 15, dd = col & 63;
                float* dst = (sel == 0) ? g_q : (sel == 1) ? g_k : g_v;
                const size_t base = ((size_t)(z * HH + hh)) * TNT;
                *(float2*)&dst[(base + (aux + row0)) * DDH + dd]     = v0;
                *(float2*)&dst[(base + (aux + row0 + 8)) * DDH + dd] = v1;
            } else {
                *(float2*)&Ceff[(size_t)row0 * ldc + col]       = v0;
                *(float2*)&Ceff[(size_t)(row0 + 8) * ldc + col] = v1;
            }
        }
    }
#undef LDGCVT
#undef STSTILE
}

// ---------------- fused flash attention, 64x64 tiles, PsT-transposed staging ----------------
__global__ void __launch_bounds__(256, 2) attn_k(const float* __restrict__ ad)
{
    extern __shared__ float sm[];
    float* QsT = sm;                    // [64][68]  QsT[d*68 + i]
    float* KsT = QsT + 64 * 68;         // [64][68]  KsT[d*68 + j]
    float* Vs  = KsT + 64 * 68;         // [64][68]  Vs [j*68 + d]
    float* PsT = Vs  + 64 * 68;         // [64][68]  PsT[j*68 + i]

    const int b  = blockIdx.z;
    const int h  = blockIdx.y;
    const int i0 = blockIdx.x * 64;
    const int tid = threadIdx.x;
    const int ty = tid >> 4, tx = tid & 15;

    const size_t plane = (size_t)(b * HH + h) * TNT;
    const float* qp = g_q + (plane + i0) * DDH;
    const float* kp = g_k + plane * DDH;
    const float* vp = g_v + plane * DDH;

    {
        const int i   = tid & 63;
        const int dc0 = (tid >> 6) * 16;
        const float* src = qp + i * DDH + dc0;
#pragma unroll
        for (int l = 0; l < 4; l++) {
            float4 v = *(const float4*)(src + l * 4);
            QsT[(dc0 + l * 4 + 0) * 68 + i] = v.x;
            QsT[(dc0 + l * 4 + 1) * 68 + i] = v.y;
            QsT[(dc0 + l * 4 + 2) * 68 + i] = v.z;
            QsT[(dc0 + l * 4 + 3) * 68 + i] = v.w;
        }
    }

    const float C1 = 0.125f * 1.4426950408889634f;
    const float C2 = 1.4426950408889634f;

    float m2[4], lsum[4], acc[4][4];
#pragma unroll
    for (int ii = 0; ii < 4; ii++) {
        m2[ii] = -1e30f; lsum[ii] = 0.f;
#pragma unroll
        for (int dd = 0; dd < 4; dd++) acc[ii][dd] = 0.f;
    }

    for (int jt = 0; jt < TNT / 64; jt++) {
        const int j0 = jt * 64;
        __syncthreads();
        {
            const int j   = tid & 63;
            const int dc0 = (tid >> 6) * 16;
            const float* src = kp + (size_t)(j0 + j) * DDH + dc0;
#pragma unroll
            for (int l = 0; l < 4; l++) {
                float4 v = *(const float4*)(src + l * 4);
                KsT[(dc0 + l * 4 + 0) * 68 + j] = v.x;
                KsT[(dc0 + l * 4 + 1) * 68 + j] = v.y;
                KsT[(dc0 + l * 4 + 2) * 68 + j] = v.z;
                KsT[(dc0 + l * 4 + 3) * 68 + j] = v.w;
            }
            const int r = tid >> 2, q4 = (tid & 3) * 4;
            const float* vsrc = vp + (size_t)(j0 + r) * DDH;
#pragma unroll
            for (int l = 0; l < 4; l++) {
                const int c = q4 + l * 16;
                *(float4*)&Vs[r * 68 + c] = *(const float4*)(vsrc + c);
            }
        }
        __syncthreads();

        float s[4][4];
#pragma unroll
        for (int ii = 0; ii < 4; ii++)
#pragma unroll
            for (int jj = 0; jj < 4; jj++) s[ii][jj] = 0.f;

#pragma unroll 8
        for (int d = 0; d < 64; d++) {
            float4 q4 = *(const float4*)&QsT[d * 68 + ty * 4];
            float4 k4 = *(const float4*)&KsT[d * 68 + tx * 4];
            float qa[4] = {q4.x, q4.y, q4.z, q4.w};
            float ka[4] = {k4.x, k4.y, k4.z, k4.w};
#pragma unroll
            for (int ii = 0; ii < 4; ii++)
#pragma unroll
                for (int jj = 0; jj < 4; jj++)
                    s[ii][jj] = fmaf(qa[ii], ka[jj], s[ii][jj]);
        }

#pragma unroll
        for (int ii = 0; ii < 4; ii++) {
            const int gi = i0 + ty * 4 + ii;
            const float4 t2  = *(const float4*)&g_T2[(plane + gi) * TNT + j0 + tx * 4];
            const float4 adv = *(const float4*)&ad[((size_t)b * TNT + gi) * TNT + j0 + tx * 4];
            float sb[4];
            sb[0] = s[ii][0] * C1 - t2.x * adv.x * C2;
            sb[1] = s[ii][1] * C1 - t2.y * adv.y * C2;
            sb[2] = s[ii][2] * C1 - t2.z * adv.z * C2;
            sb[3] = s[ii][3] * C1 - t2.w * adv.w * C2;

            float mloc = fmaxf(fmaxf(sb[0], sb[1]), fmaxf(sb[2], sb[3]));
            mloc = fmaxf(mloc, __shfl_xor_sync(0xffffffffu, mloc, 1));
            mloc = fmaxf(mloc, __shfl_xor_sync(0xffffffffu, mloc, 2));
            mloc = fmaxf(mloc, __shfl_xor_sync(0xffffffffu, mloc, 4));
            mloc = fmaxf(mloc, __shfl_xor_sync(0xffffffffu, mloc, 8));
            const float mnew  = fmaxf(m2[ii], mloc);
            const float alpha = exp2fast(m2[ii] - mnew);
            float p0 = exp2fast(sb[0] - mnew);
            float p1 = exp2fast(sb[1] - mnew);
            float p2 = exp2fast(sb[2] - mnew);
            float p3 = exp2fast(sb[3] - mnew);
            const int iy = ty * 4 + ii;
            PsT[(tx * 4 + 0) * 68 + iy] = p0;
            PsT[(tx * 4 + 1) * 68 + iy] = p1;
            PsT[(tx * 4 + 2) * 68 + iy] = p2;
            PsT[(tx * 4 + 3) * 68 + iy] = p3;
            float ls = p0 + p1 + p2 + p3;
            ls += __shfl_xor_sync(0xffffffffu, ls, 1);
            ls += __shfl_xor_sync(0xffffffffu, ls, 2);
            ls += __shfl_xor_sync(0xffffffffu, ls, 4);
            ls += __shfl_xor_sync(0xffffffffu, ls, 8);
            lsum[ii] = lsum[ii] * alpha + ls;
            m2[ii]   = mnew;
#pragma unroll
            for (int dd = 0; dd < 4; dd++) acc[ii][dd] *= alpha;
        }
        __syncthreads();

#pragma unroll 4
        for (int j = 0; j < 64; j++) {
            float4 v4 = *(const float4*)&Vs[j * 68 + tx * 4];
            float4 pv = *(const float4*)&PsT[j * 68 + ty * 4];
            float pa[4] = {pv.x, pv.y, pv.z, pv.w};
#pragma unroll
            for (int ii = 0; ii < 4; ii++) {
                acc[ii][0] = fmaf(pa[ii], v4.x, acc[ii][0]);
                acc[ii][1] = fmaf(pa[ii], v4.y, acc[ii][1]);
                acc[ii][2] = fmaf(pa[ii], v4.z, acc[ii][2]);
                acc[ii][3] = fmaf(pa[ii], v4.w, acc[ii][3]);
            }
        }
    }

#pragma unroll
    for (int ii = 0; ii < 4; ii++) {
        const float inv = 1.f / lsum[ii];
        float4 o = make_float4(acc[ii][0] * inv, acc[ii][1] * inv,
                               acc[ii][2] * inv, acc[ii][3] * inv);
        *(float4*)&g_O[((size_t)b * TNT + i0 + ty * 4 + ii) * DI + h * DDH + tx * 4] = o;
    }
}

// ---------------- launch ----------------
extern "C" void kernel_launch(void* const* d_in, const int* in_sizes, int n_in,
                              void* d_out, int out_size)
{
    const float* x0     = (const float*)d_in[0];
    const float* x1     = (const float*)d_in[1];
    const float* ad     = (const float*)d_in[2];
    const float* w_qkv0 = (const float*)d_in[5];
    const float* w_qkv1 = (const float*)d_in[6];
    const float* w_out0 = (const float*)d_in[7];
    const float* w_out1 = (const float*)d_in[8];
    const float* w_tau  = (const float*)d_in[9];
    const float* b_tau  = (const float*)d_in[10];
    float* out = (float*)d_out;

    const int attn_smem = 4 * 64 * 68 * 4;                // 69632 B
    cudaFuncSetAttribute(attn_k, cudaFuncAttributeMaxDynamicSharedMemorySize, attn_smem);
    const int tau_smem = (2 * TAU_STAGE + 128) * 4;       // 72192 B
    cudaFuncSetAttribute(tau_k, cudaFuncAttributeMaxDynamicSharedMemorySize, tau_smem);

    // w_tau -> (h, k, j) f32
    wtau_tr<<<dim3(4, 1024), 256>>>(w_tau);

    // QKV projections (tf32) -> g_q/g_k/g_v
    tgemm<0><<<dim3(24, 8, BB), 256>>>(x0, w_qkv0, nullptr, DIM0, DIM0, 3 * DI, 0,
                                       (long)N0T * DIM0, 0, 0);
    tgemm<0><<<dim3(24, 8, BB), 256>>>(x1, w_qkv1, nullptr, DIM1, DIM1, 3 * DI, 0,
                                       (long)N1T * DIM1, 0, N0T);

    // tau GEMM (dominant): T2 = Qflat @ wt2 + b_tau
    tau_k<<<dim3(16, 16, BB * HH), 256, tau_smem>>>(b_tau);

    // fused attention
    attn_k<<<dim3(TNT / 64, HH, BB), 256, attn_smem>>>(ad);

    // output projections (tf32)
    tgemm<2><<<dim3(8, 8, BB), 256>>>(nullptr, w_out0, out, DI, DI, DIM0, DIM0,
                                      0, (long)N0T * DIM0, 0);
    tgemm<2><<<dim3(6, 8, BB), 256>>>(nullptr, w_out1, out + (size_t)BB * N0T * DIM0,
                                      DI, DI, DIM1, DIM1,
                                      0, (long)N1T * DIM1, N0T * DI);
}

// round 15
// speedup vs baseline: 1.0010x; 1.0010x over previous
#include <cuda_runtime.h>
#include <math.h>
#include <stdint.h>

#define BB    2
#define N0T   1024
#define N1T   1024
#define TNT   2048
#define HH    16
#define DDH   64
#define DI    1024
#define DIM0  1024
#define DIM1  768

// ---------------- device scratch ----------------
__device__ float g_q  [(size_t)BB * HH * TNT * DDH];   // (B,H,TN,D); flat per-b (2048,1024) == reference q-reshape
__device__ float g_k  [(size_t)BB * HH * TNT * DDH];
__device__ float g_v  [(size_t)BB * HH * TNT * DDH];
__device__ float g_wt2[(size_t)HH * DI * TNT];         // (H, k=1024, j=2048)
__device__ float g_T2 [(size_t)BB * HH * TNT * TNT];   // (B,H,TN,TN)
__device__ float g_O  [(size_t)BB * TNT * DI];         // (B,TN,H*D)

// ---------------- helpers ----------------
__device__ __forceinline__ uint32_t f2tf(float f) {
    uint32_t u;
    asm("cvt.rna.tf32.f32 %0, %1;" : "=r"(u) : "f"(f));
    return u;
}
__device__ __forceinline__ void mma_tf32(float c[4],
                                         uint32_t a0, uint32_t a1, uint32_t a2, uint32_t a3,
                                         uint32_t b0, uint32_t b1) {
    asm("mma.sync.aligned.m16n8k8.row.col.f32.tf32.tf32.f32 "
        "{%0,%1,%2,%3},{%4,%5,%6,%7},{%8,%9},{%0,%1,%2,%3};"
        : "+f"(c[0]), "+f"(c[1]), "+f"(c[2]), "+f"(c[3])
        : "r"(a0), "r"(a1), "r"(a2), "r"(a3), "r"(b0), "r"(b1));
}
__device__ __forceinline__ float exp2fast(float y) {
    y = fmaxf(y, -125.f);
    float z  = y + 12582912.f;
    int   ei = __float_as_int(z) - 0x4B400000;
    float f  = y - (z - 12582912.f);
    float p  = 1.3333558e-3f;
    p = fmaf(p, f, 9.6181291e-3f);
    p = fmaf(p, f, 5.5504109e-2f);
    p = fmaf(p, f, 2.4022651e-1f);
    p = fmaf(p, f, 6.9314718e-1f);
    p = fmaf(p, f, 1.0f);
    return __int_as_float(__float_as_int(p) + (ei << 23));
}

// ---------------- w_tau transpose: (1024, j*16+h) -> (h, 1024, j) f32 ----------------
__global__ void __launch_bounds__(256) wtau_tr(const float* __restrict__ wt)
{
    __shared__ float s[512 * 17];
    const int kk = blockIdx.y;
    const int j0 = blockIdx.x * 512;
    const float* src = wt + (size_t)kk * (TNT * HH) + (size_t)j0 * HH;
    for (int t = threadIdx.x; t < 512 * 16; t += 256)
        s[(t >> 4) * 17 + (t & 15)] = src[t];
    __syncthreads();
    for (int t = threadIdx.x; t < 512 * 16; t += 256) {
        int h = t >> 9;
        int j = t & 511;
        g_wt2[(size_t)h * (DI * TNT) + (size_t)kk * TNT + j0 + j] = s[j * 17 + h];
    }
}

// ---------------- tau GEMM: 128x128 tile, K-chunk 32, single-sync double buffer ----------------
// grid (16 j, 16 i, 32 z=b*16+h), 256 threads, warp tile 64x32, 2 CTAs/SM.
#define SAW 36                         // A smem stride (floats), conflict-free frags
#define SBW 136                        // B smem stride (floats), conflict-free frags
#define TAU_STAGE (128 * SAW + 32 * SBW)   // 8960 floats per stage
#define NIT32 32
__global__ void __launch_bounds__(256, 2) tau_k(const float* __restrict__ btau)
{
    extern __shared__ __align__(16) float smem[];
    float* sbias = smem + 2 * TAU_STAGE;   // [128]

    const int tid  = threadIdx.x;
    const int lane = tid & 31, wid = tid >> 5;
    const int wm = wid >> 2, wn = wid & 3;
    const int g  = lane >> 2, tg = lane & 3;

    const int j0 = blockIdx.x * 128;
    const int i0 = blockIdx.y * 128;
    const int z  = blockIdx.z;
    const int b  = z >> 4, h = z & 15;

    const float* Ab = g_q   + (size_t)b * (TNT * DI) + (size_t)i0 * DI;
    const float* Bb = g_wt2 + (size_t)h * (DI * TNT) + j0;

    if (tid < 128) sbias[tid] = btau[(size_t)(j0 + tid) * HH + h];

    // loader mapping (identical to the proven R2 pattern, per k16 half)
    const int ar   = tid >> 2;           // 0..63 (and +64)
    const int acol = (tid & 3) * 4;      // k within half
    const int bk   = tid >> 5;           // 0..7 (and +8)
    const int bn   = (tid & 31) * 4;
    const float* Ap  = Ab + (size_t)ar * DI + acol;
    const float* Ap2 = Ap + (size_t)64 * DI;
    const float* Bp  = Bb + (size_t)bk * TNT + bn;
    const float* Bp2 = Bp + (size_t)8 * TNT;

    float acc[4][4][4];
#pragma unroll
    for (int i = 0; i < 4; i++)
#pragma unroll
        for (int j = 0; j < 4; j++)
#pragma unroll
            for (int r = 0; r < 4; r++) acc[i][j][r] = 0.f;

    uint32_t ra[8], rb[8];

// load one k16 half starting at absolute k = K0
#define LDGH(K0)                                                                 \
    {                                                                            \
        float4 a1v = *(const float4*)(Ap  + (K0));                               \
        float4 a2v = *(const float4*)(Ap2 + (K0));                               \
        float4 b1v = *(const float4*)(Bp  + (size_t)(K0) * TNT);                 \
        float4 b2v = *(const float4*)(Bp2 + (size_t)(K0) * TNT);                 \
        ra[0]=f2tf(a1v.x); ra[1]=f2tf(a1v.y); ra[2]=f2tf(a1v.z); ra[3]=f2tf(a1v.w); \
        ra[4]=f2tf(a2v.x); ra[5]=f2tf(a2v.y); ra[6]=f2tf(a2v.z); ra[7]=f2tf(a2v.w); \
        rb[0]=f2tf(b1v.x); rb[1]=f2tf(b1v.y); rb[2]=f2tf(b1v.z); rb[3]=f2tf(b1v.w); \
        rb[4]=f2tf(b2v.x); rb[5]=f2tf(b2v.y); rb[6]=f2tf(b2v.z); rb[7]=f2tf(b2v.w); \
    }
// store held half into stage S at k-offset HOFF (0 or 16)
#define STSH(S, HOFF)                                                            \
    {                                                                            \
        uint32_t* As_ = (uint32_t*)(smem + (S) * TAU_STAGE);                     \
        uint32_t* Bs_ = (uint32_t*)(smem + (S) * TAU_STAGE + 128 * SAW);         \
        *(uint4*)&As_[ar * SAW + (HOFF) + acol]        = make_uint4(ra[0], ra[1], ra[2], ra[3]); \
        *(uint4*)&As_[(ar + 64) * SAW + (HOFF) + acol] = make_uint4(ra[4], ra[5], ra[6], ra[7]); \
        *(uint4*)&Bs_[((HOFF) + bk) * SBW + bn]        = make_uint4(rb[0], rb[1], rb[2], rb[3]); \
        *(uint4*)&Bs_[((HOFF) + bk + 8) * SBW + bn]    = make_uint4(rb[4], rb[5], rb[6], rb[7]); \
    }
// one k8 MMA phase from stage base pointers
#define MMAPH(KS)                                                                \
    {                                                                            \
        uint32_t af[4][4], bf[4][2];                                             \
        _Pragma("unroll")                                                        \
        for (int mt = 0; mt < 4; mt++) {                                         \
            const int rm = wm * 64 + mt * 16 + g;                                \
            af[mt][0] = As[rm * SAW + (KS) + tg];                                \
            af[mt][1] = As[(rm + 8) * SAW + (KS) + tg];                          \
            af[mt][2] = As[rm * SAW + (KS) + tg + 4];                            \
            af[mt][3] = As[(rm + 8) * SAW + (KS) + tg + 4];                      \
        }                                                                        \
        _Pragma("unroll")                                                        \
        for (int nt = 0; nt < 4; nt++) {                                         \
            const int cn = wn * 32 + nt * 8 + g;                                 \
            bf[nt][0] = Bs[((KS) + tg) * SBW + cn];                              \
            bf[nt][1] = Bs[((KS) + tg + 4) * SBW + cn];                          \
        }                                                                        \
        _Pragma("unroll")                                                        \
        for (int mt = 0; mt < 4; mt++)                                           \
            _Pragma("unroll")                                                    \
            for (int nt = 0; nt < 4; nt++)                                       \
                mma_tf32(acc[mt][nt], af[mt][0], af[mt][1], af[mt][2], af[mt][3],\
                         bf[nt][0], bf[nt][1]);                                  \
    }

    // prologue: fill stage 0 (both halves)
    LDGH(0);  STSH(0, 0);
    LDGH(16); STSH(0, 16);
    __syncthreads();

    int buf = 0;
    for (int it = 0; it < NIT32; it++) {
        const int k0 = it * 32;
        const bool nxt = (it + 1) < NIT32;
        const uint32_t* As = (const uint32_t*)(smem + buf * TAU_STAGE);
        const uint32_t* Bs = (const uint32_t*)(smem + buf * TAU_STAGE + 128 * SAW);

        if (nxt) LDGH(k0 + 32);
        MMAPH(0);
        MMAPH(8);
        if (nxt) { STSH(buf ^ 1, 0); LDGH(k0 + 48); }
        MMAPH(16);
        if (nxt) STSH(buf ^ 1, 16);
        MMAPH(24);
        __syncthreads();
        buf ^= 1;
    }
#undef LDGH
#undef STSH
#undef MMAPH

    // epilogue: + b_tau, write g_T2
#pragma unroll
    for (int mt = 0; mt < 4; mt++) {
        const int row0 = i0 + wm * 64 + mt * 16 + g;
#pragma unroll
        for (int nt = 0; nt < 4; nt++) {
            const int col = wn * 32 + nt * 8 + tg * 2;
            const float b0 = sbias[col], b1 = sbias[col + 1];
            float2 v0 = make_float2(acc[mt][nt][0] + b0, acc[mt][nt][1] + b1);
            float2 v1 = make_float2(acc[mt][nt][2] + b0, acc[mt][nt][3] + b1);
            float* base = g_T2 + ((size_t)z * TNT + row0) * TNT + j0 + col;
            *(float2*)base = v0;
            *(float2*)(base + (size_t)8 * TNT) = v1;
        }
    }
}

// ---------------- TF32 legacy GEMM (qkv / out), 128x128x16 ----------------
template<int MODE>
__global__ void __launch_bounds__(256, 2)
tgemm(const float* __restrict__ A, const float* __restrict__ Bm, float* __restrict__ C,
      int K, int lda, int ldb, int ldc,
      long strideA, long strideC, int aux)
{
    __shared__ uint32_t As[2][128 * 20];
    __shared__ uint32_t Bs[2][16 * 136];

    const int z = blockIdx.z;
    const float* Aeff;
    const float* Beff;
    float*       Ceff = nullptr;

    if (MODE == 2) {
        Aeff = g_O + (size_t)aux + (size_t)z * ((size_t)TNT * DI);
        Beff = Bm;
        Ceff = C + (size_t)z * strideC;
    } else {
        Aeff = A + (size_t)z * strideA;
        Beff = Bm;
    }

    const int tid  = threadIdx.x;
    const int lane = tid & 31, wid = tid >> 5;
    const int wm = wid >> 2, wn = wid & 3;
    const int g  = lane >> 2, tg = lane & 3;
    const int m0 = blockIdx.y * 128, n0 = blockIdx.x * 128;

    float acc[4][4][4];
#pragma unroll
    for (int i = 0; i < 4; i++)
#pragma unroll
        for (int j = 0; j < 4; j++)
#pragma unroll
            for (int r = 0; r < 4; r++) acc[i][j][r] = 0.f;

    const int ar   = tid >> 2;
    const int acol = (tid & 3) * 4;
    const int bk   = tid >> 5;
    const int bn   = (tid & 31) * 4;
    const float* Ap  = Aeff + (size_t)(m0 + ar) * lda + acol;
    const float* Ap2 = Ap + (size_t)64 * lda;
    const float* Bp  = Beff + (size_t)bk * ldb + n0 + bn;
    const float* Bp2 = Bp + (size_t)8 * ldb;

    uint32_t ra[8], rb[8];

#define LDGCVT(K0)                                                              \
    {                                                                           \
        float4 a1v = *(const float4*)(Ap  + (K0));                              \
        float4 a2v = *(const float4*)(Ap2 + (K0));                              \
        float4 b1v = *(const float4*)(Bp  + (size_t)(K0) * ldb);                \
        float4 b2v = *(const float4*)(Bp2 + (size_t)(K0) * ldb);                \
        ra[0]=f2tf(a1v.x); ra[1]=f2tf(a1v.y); ra[2]=f2tf(a1v.z); ra[3]=f2tf(a1v.w); \
        ra[4]=f2tf(a2v.x); ra[5]=f2tf(a2v.y); ra[6]=f2tf(a2v.z); ra[7]=f2tf(a2v.w); \
        rb[0]=f2tf(b1v.x); rb[1]=f2tf(b1v.y); rb[2]=f2tf(b1v.z); rb[3]=f2tf(b1v.w); \
        rb[4]=f2tf(b2v.x); rb[5]=f2tf(b2v.y); rb[6]=f2tf(b2v.z); rb[7]=f2tf(b2v.w); \
    }
#define STSTILE(S)                                                              \
    {                                                                           \
        *(uint4*)&As[S][ar * 20 + acol]        = make_uint4(ra[0], ra[1], ra[2], ra[3]); \
        *(uint4*)&As[S][(ar + 64) * 20 + acol] = make_uint4(ra[4], ra[5], ra[6], ra[7]); \
        *(uint4*)&Bs[S][bk * 136 + bn]         = make_uint4(rb[0], rb[1], rb[2], rb[3]); \
        *(uint4*)&Bs[S][(bk + 8) * 136 + bn]   = make_uint4(rb[4], rb[5], rb[6], rb[7]); \
    }

    LDGCVT(0);
    STSTILE(0);
    __syncthreads();

    int buf = 0;
    for (int k0 = 0; k0 < K; k0 += 16) {
        const bool nxt = (k0 + 16) < K;
        if (nxt) LDGCVT(k0 + 16);
#pragma unroll
        for (int ks = 0; ks < 16; ks += 8) {
            uint32_t af[4][4], bf[4][2];
#pragma unroll
            for (int mt = 0; mt < 4; mt++) {
                const int rm = wm * 64 + mt * 16 + g;
                af[mt][0] = As[buf][rm * 20 + ks + tg];
                af[mt][1] = As[buf][(rm + 8) * 20 + ks + tg];
                af[mt][2] = As[buf][rm * 20 + ks + tg + 4];
                af[mt][3] = As[buf][(rm + 8) * 20 + ks + tg + 4];
            }
#pragma unroll
            for (int nt = 0; nt < 4; nt++) {
                const int cn = wn * 32 + nt * 8 + g;
                bf[nt][0] = Bs[buf][(ks + tg) * 136 + cn];
                bf[nt][1] = Bs[buf][(ks + tg + 4) * 136 + cn];
            }
#pragma unroll
            for (int mt = 0; mt < 4; mt++)
#pragma unroll
                for (int nt = 0; nt < 4; nt++)
                    mma_tf32(acc[mt][nt], af[mt][0], af[mt][1], af[mt][2], af[mt][3],
                             bf[nt][0], bf[nt][1]);
        }
        if (nxt) STSTILE(buf ^ 1);
        __syncthreads();
        buf ^= 1;
    }

#pragma unroll
    for (int mt = 0; mt < 4; mt++) {
        const int row0 = m0 + wm * 64 + mt * 16 + g;
#pragma unroll
        for (int nt = 0; nt < 4; nt++) {
            const int col = n0 + wn * 32 + nt * 8 + tg * 2;
            float2 v0 = make_float2(acc[mt][nt][0], acc[mt][nt][1]);
            float2 v1 = make_float2(acc[mt][nt][2], acc[mt][nt][3]);
            if (MODE == 0) {
                const int sel = col >> 10, hh = (col >> 6) & 15, dd = col & 63;
                float* dst = (sel == 0) ? g_q : (sel == 1) ? g_k : g_v;
                const size_t base = ((size_t)(z * HH + hh)) * TNT;
                *(float2*)&dst[(base + (aux + row0)) * DDH + dd]     = v0;
                *(float2*)&dst[(base + (aux + row0 + 8)) * DDH + dd] = v1;
            } else {
                *(float2*)&Ceff[(size_t)row0 * ldc + col]       = v0;
                *(float2*)&Ceff[(size_t)(row0 + 8) * ldc + col] = v1;
            }
        }
    }
#undef LDGCVT
#undef STSTILE
}

// ---------------- fused flash attention, 64x64 tiles, PsT-transposed staging ----------------
__global__ void __launch_bounds__(256, 2) attn_k(const float* __restrict__ ad)
{
    extern __shared__ float sm[];
    float* QsT = sm;                    // [64][68]  QsT[d*68 + i]
    float* KsT = QsT + 64 * 68;         // [64][68]  KsT[d*68 + j]
    float* Vs  = KsT + 64 * 68;         // [64][68]  Vs [j*68 + d]
    float* PsT = Vs  + 64 * 68;         // [64][68]  PsT[j*68 + i]

    const int b  = blockIdx.z;
    const int h  = blockIdx.y;
    const int i0 = blockIdx.x * 64;
    const int tid = threadIdx.x;
    const int ty = tid >> 4, tx = tid & 15;

    const size_t plane = (size_t)(b * HH + h) * TNT;
    const float* qp = g_q + (plane + i0) * DDH;
    const float* kp = g_k + plane * DDH;
    const float* vp = g_v + plane * DDH;

    {
        const int i   = tid & 63;
        const int dc0 = (tid >> 6) * 16;
        const float* src = qp + i * DDH + dc0;
#pragma unroll
        for (int l = 0; l < 4; l++) {
            float4 v = *(const float4*)(src + l * 4);
            QsT[(dc0 + l * 4 + 0) * 68 + i] = v.x;
            QsT[(dc0 + l * 4 + 1) * 68 + i] = v.y;
            QsT[(dc0 + l * 4 + 2) * 68 + i] = v.z;
            QsT[(dc0 + l * 4 + 3) * 68 + i] = v.w;
        }
    }

    const float C1 = 0.125f * 1.4426950408889634f;
    const float C2 = 1.4426950408889634f;

    float m2[4], lsum[4], acc[4][4];
#pragma unroll
    for (int ii = 0; ii < 4; ii++) {
        m2[ii] = -1e30f; lsum[ii] = 0.f;
#pragma unroll
        for (int dd = 0; dd < 4; dd++) acc[ii][dd] = 0.f;
    }

    for (int jt = 0; jt < TNT / 64; jt++) {
        const int j0 = jt * 64;
        __syncthreads();
        {
            const int j   = tid & 63;
            const int dc0 = (tid >> 6) * 16;
            const float* src = kp + (size_t)(j0 + j) * DDH + dc0;
#pragma unroll
            for (int l = 0; l < 4; l++) {
                float4 v = *(const float4*)(src + l * 4);
                KsT[(dc0 + l * 4 + 0) * 68 + j] = v.x;
                KsT[(dc0 + l * 4 + 1) * 68 + j] = v.y;
                KsT[(dc0 + l * 4 + 2) * 68 + j] = v.z;
                KsT[(dc0 + l * 4 + 3) * 68 + j] = v.w;
            }
            const int r = tid >> 2, q4 = (tid & 3) * 4;
            const float* vsrc = vp + (size_t)(j0 + r) * DDH;
#pragma unroll
            for (int l = 0; l < 4; l++) {
                const int c = q4 + l * 16;
                *(float4*)&Vs[r * 68 + c] = *(const float4*)(vsrc + c);
            }
        }
        __syncthreads();

        float s[4][4];
#pragma unroll
        for (int ii = 0; ii < 4; ii++)
#pragma unroll
            for (int jj = 0; jj < 4; jj++) s[ii][jj] = 0.f;

#pragma unroll 8
        for (int d = 0; d < 64; d++) {
            float4 q4 = *(const float4*)&QsT[d * 68 + ty * 4];
            float4 k4 = *(const float4*)&KsT[d * 68 + tx * 4];
            float qa[4] = {q4.x, q4.y, q4.z, q4.w};
            float ka[4] = {k4.x, k4.y, k4.z, k4.w};
#pragma unroll
            for (int ii = 0; ii < 4; ii++)
#pragma unroll
                for (int jj = 0; jj < 4; jj++)
                    s[ii][jj] = fmaf(qa[ii], ka[jj], s[ii][jj]);
        }

#pragma unroll
        for (int ii = 0; ii < 4; ii++) {
            const int gi = i0 + ty * 4 + ii;
            const float4 t2  = *(const float4*)&g_T2[(plane + gi) * TNT + j0 + tx * 4];
            const float4 adv = *(const float4*)&ad[((size_t)b * TNT + gi) * TNT + j0 + tx * 4];
            float sb[4];
            sb[0] = s[ii][0] * C1 - t2.x * adv.x * C2;
            sb[1] = s[ii][1] * C1 - t2.y * adv.y * C2;
            sb[2] = s[ii][2] * C1 - t2.z * adv.z * C2;
            sb[3] = s[ii][3] * C1 - t2.w * adv.w * C2;

            float mloc = fmaxf(fmaxf(sb[0], sb[1]), fmaxf(sb[2], sb[3]));
            mloc = fmaxf(mloc, __shfl_xor_sync(0xffffffffu, mloc, 1));
            mloc = fmaxf(mloc, __shfl_xor_sync(0xffffffffu, mloc, 2));
            mloc = fmaxf(mloc, __shfl_xor_sync(0xffffffffu, mloc, 4));
            mloc = fmaxf(mloc, __shfl_xor_sync(0xffffffffu, mloc, 8));
            const float mnew  = fmaxf(m2[ii], mloc);
            const float alpha = exp2fast(m2[ii] - mnew);
            float p0 = exp2fast(sb[0] - mnew);
            float p1 = exp2fast(sb[1] - mnew);
            float p2 = exp2fast(sb[2] - mnew);
            float p3 = exp2fast(sb[3] - mnew);
            const int iy = ty * 4 + ii;
            PsT[(tx * 4 + 0) * 68 + iy] = p0;
            PsT[(tx * 4 + 1) * 68 + iy] = p1;
            PsT[(tx * 4 + 2) * 68 + iy] = p2;
            PsT[(tx * 4 + 3) * 68 + iy] = p3;
            float ls = p0 + p1 + p2 + p3;
            ls += __shfl_xor_sync(0xffffffffu, ls, 1);
            ls += __shfl_xor_sync(0xffffffffu, ls, 2);
            ls += __shfl_xor_sync(0xffffffffu, ls, 4);
            ls += __shfl_xor_sync(0xffffffffu, ls, 8);
            lsum[ii] = lsum[ii] * alpha + ls;
            m2[ii]   = mnew;
#pragma unroll
            for (int dd = 0; dd < 4; dd++) acc[ii][dd] *= alpha;
        }
        __syncthreads();

#pragma unroll 4
        for (int j = 0; j < 64; j++) {
            float4 v4 = *(const float4*)&Vs[j * 68 + tx * 4];
            float4 pv = *(const float4*)&PsT[j * 68 + ty * 4];
            float pa[4] = {pv.x, pv.y, pv.z, pv.w};
#pragma unroll
            for (int ii = 0; ii < 4; ii++) {
                acc[ii][0] = fmaf(pa[ii], v4.x, acc[ii][0]);
                acc[ii][1] = fmaf(pa[ii], v4.y, acc[ii][1]);
                acc[ii][2] = fmaf(pa[ii], v4.z, acc[ii][2]);
                acc[ii][3] = fmaf(pa[ii], v4.w, acc[ii][3]);
            }
        }
    }

#pragma unroll
    for (int ii = 0; ii < 4; ii++) {
        const float inv = 1.f / lsum[ii];
        float4 o = make_float4(acc[ii][0] * inv, acc[ii][1] * inv,
                               acc[ii][2] * inv, acc[ii][3] * inv);
        *(float4*)&g_O[((size_t)b * TNT + i0 + ty * 4 + ii) * DI + h * DDH + tx * 4] = o;
    }
}

// ---------------- launch ----------------
extern "C" void kernel_launch(void* const* d_in, const int* in_sizes, int n_in,
                              void* d_out, int out_size)
{
    const float* x0     = (const float*)d_in[0];
    const float* x1     = (const float*)d_in[1];
    const float* ad     = (const float*)d_in[2];
    const float* w_qkv0 = (const float*)d_in[5];
    const float* w_qkv1 = (const float*)d_in[6];
    const float* w_out0 = (const float*)d_in[7];
    const float* w_out1 = (const float*)d_in[8];
    const float* w_tau  = (const float*)d_in[9];
    const float* b_tau  = (const float*)d_in[10];
    float* out = (float*)d_out;

    const int attn_smem = 4 * 64 * 68 * 4;                // 69632 B
    cudaFuncSetAttribute(attn_k, cudaFuncAttributeMaxDynamicSharedMemorySize, attn_smem);
    const int tau_smem = (2 * TAU_STAGE + 128) * 4;       // 72192 B
    cudaFuncSetAttribute(tau_k, cudaFuncAttributeMaxDynamicSharedMemorySize, tau_smem);

    // w_tau -> (h, k, j) f32
    wtau_tr<<<dim3(4, 1024), 256>>>(w_tau);

    // QKV projections (tf32) -> g_q/g_k/g_v
    tgemm<0><<<dim3(24, 8, BB), 256>>>(x0, w_qkv0, nullptr, DIM0, DIM0, 3 * DI, 0,
                                       (long)N0T * DIM0, 0, 0);
    tgemm<0><<<dim3(24, 8, BB), 256>>>(x1, w_qkv1, nullptr, DIM1, DIM1, 3 * DI, 0,
                                       (long)N1T * DIM1, 0, N0T);

    // tau GEMM (dominant): T2 = Qflat @ wt2 + b_tau
    tau_k<<<dim3(16, 16, BB * HH), 256, tau_smem>>>(b_tau);

    // fused attention
    attn_k<<<dim3(TNT / 64, HH, BB), 256, attn_smem>>>(ad);

    // output projections (tf32)
    tgemm<2><<<dim3(8, 8, BB), 256>>>(nullptr, w_out0, out, DI, DI, DIM0, DIM0,
                                      0, (long)N0T * DIM0, 0);
    tgemm<2><<<dim3(6, 8, BB), 256>>>(nullptr, w_out1, out + (size_t)BB * N0T * DIM0,
                                      DI, DI, DIM1, DIM1,
                                      0, (long)N1T * DIM1, N0T * DI);
}